// round 5
// baseline (speedup 1.0000x reference)
#include <cuda_runtime.h>

// BaseGraphPooling: segment-mean over sorted node_batch.
// node_h: [N,128] fp32, node_batch: [N] int32 sorted, out: [G,128] fp32.
//
// 2 launches (PDL-chained); no front-side zeroing kernel:
//  1) chunk_sum : 1184 CTAs (148 SMs x 8), fixed contiguous row chunks ->
//                 perfect per-SM byte balance; sorted indices => 1-2 segments
//                 per chunk; partial sums flushed via red.global.add.v4.f32
//                 into a __device__ scratch buffer (zero on module load,
//                 re-zeroed by divide each launch -> graph-replay safe).
//  2) divide    : per-graph count via binary search (overlaps chunk_sum tail
//                 via PDL), scales scratch by 1/max(count,1) into d_out, then
//                 zeroes scratch for the next replay.

#define NUM_CTAS 1184       // 148 SMs * 8 CTAs/SM, exactly one wave
#define MAX_G    1024

__device__ float4 g_scratch[MAX_G * 32];   // zero-initialized at load

__device__ __forceinline__ int lower_bound_i32(const int* __restrict__ a,
                                               int n, int key) {
    int lo = 0, hi = n;
    while (lo < hi) {
        int mid = (lo + hi) >> 1;
        if (a[mid] < key) lo = mid + 1; else hi = mid;
    }
    return lo;
}

__device__ __forceinline__ float4 f4add(float4 a, float4 b) {
    a.x += b.x; a.y += b.y; a.z += b.z; a.w += b.w; return a;
}

__device__ __forceinline__ void red_add_v4(float4* addr, float4 v) {
    asm volatile("red.global.add.v4.f32 [%0], {%1, %2, %3, %4};"
                 :: "l"(addr), "f"(v.x), "f"(v.y), "f"(v.z), "f"(v.w)
                 : "memory");
}

__global__ __launch_bounds__(256, 8)
void chunk_sum_kernel(const float4* __restrict__ h,    // N*32 float4
                      const int* __restrict__ batch,   // N int32, sorted
                      int N, int rows_per_cta) {
    const int tid = threadIdx.x;
    const int c   = tid & 31;   // float4 column (0..31)
    const int r   = tid >> 5;   // row phase (0..7)

    int c0 = blockIdx.x * rows_per_cta;
    int c1 = min(c0 + rows_per_cta, N);
    if (c0 >= c1) return;

    __shared__ float4 smem[256];

    int s = c0;
    while (s < c1) {
        const int g = batch[s];                 // uniform: current segment id
        // upper_bound(g) within [s, c1) -> end of this sub-segment
        int lo = s, hi = c1;
        while (lo < hi) {
            int mid = (lo + hi) >> 1;
            if (batch[mid] <= g) lo = mid + 1; else hi = mid;
        }
        const int e = lo;

        float4 a0 = make_float4(0.f, 0.f, 0.f, 0.f);
        float4 a1 = a0, a2 = a0, a3 = a0;

        int i = s + r;
        for (; i + 24 < e; i += 32) {
            float4 v0 = __ldcs(&h[(size_t)(i     ) * 32 + c]);
            float4 v1 = __ldcs(&h[(size_t)(i +  8) * 32 + c]);
            float4 v2 = __ldcs(&h[(size_t)(i + 16) * 32 + c]);
            float4 v3 = __ldcs(&h[(size_t)(i + 24) * 32 + c]);
            a0 = f4add(a0, v0);
            a1 = f4add(a1, v1);
            a2 = f4add(a2, v2);
            a3 = f4add(a3, v3);
        }
        for (; i < e; i += 8)
            a0 = f4add(a0, __ldcs(&h[(size_t)i * 32 + c]));

        smem[tid] = f4add(f4add(a0, a1), f4add(a2, a3));
        __syncthreads();

        if (r == 0) {
            float4 acc = smem[c];
            #pragma unroll
            for (int p = 1; p < 8; p++)
                acc = f4add(acc, smem[p * 32 + c]);
            red_add_v4(&g_scratch[(size_t)g * 32 + c], acc);
        }
        __syncthreads();   // smem reuse safety for next sub-segment

        s = e;
    }
}

__global__ void divide_kernel(const int* __restrict__ batch,
                              float4* __restrict__ out,
                              int N) {
    const int g = blockIdx.x;
    const int c = threadIdx.x;   // 0..31
    // Binary searches depend only on batch -> overlap chunk_sum's tail.
    const int start = lower_bound_i32(batch, N, g);
    const int end   = lower_bound_i32(batch, N, g + 1);
    const float inv = 1.0f / (float)max(end - start, 1);

    cudaGridDependencySynchronize();   // wait for all chunk_sum atomics

    float4 v = g_scratch[(size_t)g * 32 + c];
    // Re-zero scratch for the next graph replay (self-cleaning accumulator).
    g_scratch[(size_t)g * 32 + c] = make_float4(0.f, 0.f, 0.f, 0.f);
    v.x *= inv; v.y *= inv; v.z *= inv; v.w *= inv;
    out[(size_t)g * 32 + c] = v;
}

extern "C" void kernel_launch(void* const* d_in, const int* in_sizes, int n_in,
                              void* d_out, int out_size) {
    const float4* h     = (const float4*)d_in[0];
    const int*    batch = (const int*)d_in[1];
    const int N = in_sizes[1];       // number of nodes
    const int G = out_size / 128;    // number of graphs

    int rows_per_cta = (N + NUM_CTAS - 1) / NUM_CTAS;
    chunk_sum_kernel<<<NUM_CTAS, 256>>>(h, batch, N, rows_per_cta);

    cudaLaunchAttribute pdl[1];
    pdl[0].id = cudaLaunchAttributeProgrammaticStreamSerialization;
    pdl[0].val.programmaticStreamSerializationAllowed = 1;

    cudaLaunchConfig_t cfg = {};
    cfg.gridDim  = dim3(G, 1, 1);
    cfg.blockDim = dim3(32, 1, 1);
    cfg.stream   = 0;
    cfg.attrs    = pdl;
    cfg.numAttrs = 1;
    cudaLaunchKernelEx(&cfg, divide_kernel, batch, (float4*)d_out, N);
}

// round 6
// speedup vs baseline: 1.0553x; 1.0553x over previous
#include <cuda_runtime.h>

// BaseGraphPooling: segment-mean over sorted node_batch.
// node_h: [N,128] fp32, node_batch: [N] int32 sorted, out: [G,128] fp32.
//
// 2 launches (PDL-chained), self-cleaning device scratch (no zeroing kernel):
//  1) chunk_sum : 1184 CTAs (148 SMs x 8), fixed contiguous row chunks ->
//                 perfect per-SM byte balance. Sorted indices => each chunk
//                 spans ~1-2 segments. Partial sums flushed via
//                 red.global.add.v4.f32 into g_scratch; sub-segment LENGTHS
//                 flushed via one int atomic into g_count (kills the binary
//                 searches that made the old epilogue a 20us latency chain).
//  2) divide    : straight-line: load count + scratch, scale, store to d_out,
//                 re-zero scratch/count for the next graph replay.

#define NUM_CTAS 1184       // 148 SMs * 8 CTAs/SM, exactly one wave
#define MAX_G    1024

__device__ float4 g_scratch[MAX_G * 32];   // zero-initialized at load
__device__ int    g_count[MAX_G];          // zero-initialized at load

__device__ __forceinline__ float4 f4add(float4 a, float4 b) {
    a.x += b.x; a.y += b.y; a.z += b.z; a.w += b.w; return a;
}

__device__ __forceinline__ void red_add_v4(float4* addr, float4 v) {
    asm volatile("red.global.add.v4.f32 [%0], {%1, %2, %3, %4};"
                 :: "l"(addr), "f"(v.x), "f"(v.y), "f"(v.z), "f"(v.w)
                 : "memory");
}

__device__ __forceinline__ void red_add_s32(int* addr, int v) {
    asm volatile("red.global.add.s32 [%0], %1;" :: "l"(addr), "r"(v) : "memory");
}

__global__ __launch_bounds__(256, 8)
void chunk_sum_kernel(const float4* __restrict__ h,    // N*32 float4
                      const int* __restrict__ batch,   // N int32, sorted
                      int N, int rows_per_cta) {
    const int tid = threadIdx.x;
    const int c   = tid & 31;   // float4 column (0..31)
    const int r   = tid >> 5;   // row phase (0..7)

    int c0 = blockIdx.x * rows_per_cta;
    int c1 = min(c0 + rows_per_cta, N);
    if (c0 >= c1) return;

    __shared__ float4 smem[256];

    int s = c0;
    while (s < c1) {
        const int g = batch[s];                 // uniform: current segment id
        // upper_bound(g) within [s, c1) -> end of this sub-segment
        int lo = s, hi = c1;
        while (lo < hi) {
            int mid = (lo + hi) >> 1;
            if (batch[mid] <= g) lo = mid + 1; else hi = mid;
        }
        const int e = lo;

        float4 a0 = make_float4(0.f, 0.f, 0.f, 0.f);
        float4 a1 = a0, a2 = a0, a3 = a0;

        int i = s + r;
        for (; i + 24 < e; i += 32) {
            float4 v0 = __ldcs(&h[(size_t)(i     ) * 32 + c]);
            float4 v1 = __ldcs(&h[(size_t)(i +  8) * 32 + c]);
            float4 v2 = __ldcs(&h[(size_t)(i + 16) * 32 + c]);
            float4 v3 = __ldcs(&h[(size_t)(i + 24) * 32 + c]);
            a0 = f4add(a0, v0);
            a1 = f4add(a1, v1);
            a2 = f4add(a2, v2);
            a3 = f4add(a3, v3);
        }
        for (; i < e; i += 8)
            a0 = f4add(a0, __ldcs(&h[(size_t)i * 32 + c]));

        smem[tid] = f4add(f4add(a0, a1), f4add(a2, a3));
        __syncthreads();

        if (tid == 0)
            red_add_s32(&g_count[g], e - s);   // segment length contribution
        if (r == 0) {
            float4 acc = smem[c];
            #pragma unroll
            for (int p = 1; p < 8; p++)
                acc = f4add(acc, smem[p * 32 + c]);
            red_add_v4(&g_scratch[(size_t)g * 32 + c], acc);
        }
        __syncthreads();   // smem reuse safety for next sub-segment

        s = e;
    }
}

__global__ void divide_kernel(float4* __restrict__ out) {
    const int g = blockIdx.x;
    const int c = threadIdx.x;   // 0..31

    cudaGridDependencySynchronize();   // wait for all chunk_sum atomics

    const int cnt = g_count[g];
    const float inv = 1.0f / (float)max(cnt, 1);

    float4 v = g_scratch[(size_t)g * 32 + c];
    // Self-cleaning for the next graph replay.
    g_scratch[(size_t)g * 32 + c] = make_float4(0.f, 0.f, 0.f, 0.f);
    if (c == 0) g_count[g] = 0;

    v.x *= inv; v.y *= inv; v.z *= inv; v.w *= inv;
    out[(size_t)g * 32 + c] = v;
}

extern "C" void kernel_launch(void* const* d_in, const int* in_sizes, int n_in,
                              void* d_out, int out_size) {
    const float4* h     = (const float4*)d_in[0];
    const int*    batch = (const int*)d_in[1];
    const int N = in_sizes[1];       // number of nodes
    const int G = out_size / 128;    // number of graphs

    int rows_per_cta = (N + NUM_CTAS - 1) / NUM_CTAS;
    chunk_sum_kernel<<<NUM_CTAS, 256>>>(h, batch, N, rows_per_cta);

    cudaLaunchAttribute pdl[1];
    pdl[0].id = cudaLaunchAttributeProgrammaticStreamSerialization;
    pdl[0].val.programmaticStreamSerializationAllowed = 1;

    cudaLaunchConfig_t cfg = {};
    cfg.gridDim  = dim3(G, 1, 1);
    cfg.blockDim = dim3(32, 1, 1);
    cfg.stream   = 0;
    cfg.attrs    = pdl;
    cfg.numAttrs = 1;
    cudaLaunchKernelEx(&cfg, divide_kernel, (float4*)d_out);
}

// round 7
// speedup vs baseline: 1.1146x; 1.0562x over previous
#include <cuda_runtime.h>

// BaseGraphPooling: segment-mean over sorted node_batch.
// node_h: [N,128] fp32, node_batch: [N] int32 sorted, out: [G,128] fp32.
//
// 2 launches (PDL-chained), self-cleaning device scratch:
//  1) chunk_sum : 1184 CTAs (148 SMs x 8), fixed contiguous row chunks ->
//                 perfect per-SM byte balance. The CTA's index slice is staged
//                 into smem with one coalesced burst; sub-segment boundaries
//                 are found by smem binary search (no serial DRAM chases).
//                 Partial sums -> red.global.add.v4.f32 into g_scratch;
//                 sub-segment lengths -> int atomic into g_count.
//  2) divide    : 256-thread blocks, one (g,c) pair per thread: load count +
//                 scratch, scale, store to d_out, re-zero scratch for replay.

#define NUM_CTAS 1184       // 148 SMs * 8 CTAs/SM, exactly one wave
#define MAX_G    1024
#define MAX_RPC  1728       // max rows_per_cta supported by smem staging

__device__ float4 g_scratch[MAX_G * 32];   // zero-initialized at load
__device__ int    g_count[MAX_G];          // zero-initialized at load

__device__ __forceinline__ float4 f4add(float4 a, float4 b) {
    a.x += b.x; a.y += b.y; a.z += b.z; a.w += b.w; return a;
}

__device__ __forceinline__ void red_add_v4(float4* addr, float4 v) {
    asm volatile("red.global.add.v4.f32 [%0], {%1, %2, %3, %4};"
                 :: "l"(addr), "f"(v.x), "f"(v.y), "f"(v.z), "f"(v.w)
                 : "memory");
}

__device__ __forceinline__ void red_add_s32(int* addr, int v) {
    asm volatile("red.global.add.s32 [%0], %1;" :: "l"(addr), "r"(v) : "memory");
}

__global__ __launch_bounds__(256, 8)
void chunk_sum_kernel(const float4* __restrict__ h,    // N*32 float4
                      const int* __restrict__ batch,   // N int32, sorted
                      int N, int rows_per_cta) {
    const int tid = threadIdx.x;
    const int c   = tid & 31;   // float4 column (0..31)
    const int r   = tid >> 5;   // row phase (0..7)

    const int c0 = blockIdx.x * rows_per_cta;
    const int c1 = min(c0 + rows_per_cta, N);
    if (c0 >= c1) return;
    const int len = c1 - c0;

    __shared__ float4 smem[256];
    __shared__ int    sb[MAX_RPC];

    // Stage this CTA's index slice into smem (coalesced, high-MLP burst).
    for (int i = tid; i < len; i += 256)
        sb[i] = batch[c0 + i];
    __syncthreads();

    int s = c0;
    while (s < c1) {
        const int g = sb[s - c0];               // current segment id (uniform)
        // upper_bound(g) within [s, c1) via smem binary search (~11 LDS)
        int lo = s, hi = c1;
        while (lo < hi) {
            int mid = (lo + hi) >> 1;
            if (sb[mid - c0] <= g) lo = mid + 1; else hi = mid;
        }
        const int e = lo;

        float4 a0 = make_float4(0.f, 0.f, 0.f, 0.f);
        float4 a1 = a0, a2 = a0, a3 = a0;

        int i = s + r;
        for (; i + 24 < e; i += 32) {
            float4 v0 = __ldcs(&h[(size_t)(i     ) * 32 + c]);
            float4 v1 = __ldcs(&h[(size_t)(i +  8) * 32 + c]);
            float4 v2 = __ldcs(&h[(size_t)(i + 16) * 32 + c]);
            float4 v3 = __ldcs(&h[(size_t)(i + 24) * 32 + c]);
            a0 = f4add(a0, v0);
            a1 = f4add(a1, v1);
            a2 = f4add(a2, v2);
            a3 = f4add(a3, v3);
        }
        for (; i < e; i += 8)
            a0 = f4add(a0, __ldcs(&h[(size_t)i * 32 + c]));

        smem[tid] = f4add(f4add(a0, a1), f4add(a2, a3));
        __syncthreads();

        if (tid == 0)
            red_add_s32(&g_count[g], e - s);   // segment length contribution
        if (r == 0) {
            float4 acc = smem[c];
            #pragma unroll
            for (int p = 1; p < 8; p++)
                acc = f4add(acc, smem[p * 32 + c]);
            red_add_v4(&g_scratch[(size_t)g * 32 + c], acc);
        }
        __syncthreads();   // smem reuse safety for next sub-segment

        s = e;
    }
}

__global__ void divide_kernel(float4* __restrict__ out, int G) {
    const int idx = blockIdx.x * blockDim.x + threadIdx.x;
    const int g = idx >> 5;
    const int c = idx & 31;

    cudaGridDependencySynchronize();   // wait for all chunk_sum atomics

    if (g >= G) return;

    const int cnt = g_count[g];
    const float inv = 1.0f / (float)max(cnt, 1);

    float4 v = g_scratch[(size_t)g * 32 + c];
    // Self-cleaning for the next graph replay.
    g_scratch[(size_t)g * 32 + c] = make_float4(0.f, 0.f, 0.f, 0.f);
    if (c == 0) g_count[g] = 0;

    v.x *= inv; v.y *= inv; v.z *= inv; v.w *= inv;
    out[(size_t)g * 32 + c] = v;
}

extern "C" void kernel_launch(void* const* d_in, const int* in_sizes, int n_in,
                              void* d_out, int out_size) {
    const float4* h     = (const float4*)d_in[0];
    const int*    batch = (const int*)d_in[1];
    const int N = in_sizes[1];       // number of nodes
    const int G = out_size / 128;    // number of graphs

    int rows_per_cta = (N + NUM_CTAS - 1) / NUM_CTAS;
    // smem staging supports rows_per_cta <= MAX_RPC (true for N=2M, 1184 CTAs)
    chunk_sum_kernel<<<NUM_CTAS, 256>>>(h, batch, N, rows_per_cta);

    cudaLaunchAttribute pdl[1];
    pdl[0].id = cudaLaunchAttributeProgrammaticStreamSerialization;
    pdl[0].val.programmaticStreamSerializationAllowed = 1;

    cudaLaunchConfig_t cfg = {};
    cfg.gridDim  = dim3((G * 32 + 255) / 256, 1, 1);
    cfg.blockDim = dim3(256, 1, 1);
    cfg.stream   = 0;
    cfg.attrs    = pdl;
    cfg.numAttrs = 1;
    cudaLaunchKernelEx(&cfg, divide_kernel, (float4*)d_out, G);
}